// round 5
// baseline (speedup 1.0000x reference)
#include <cuda_runtime.h>
#include <math.h>

#define Nn 50000
#define Ee 800000
#define DD 64
#define LRA 0.2f

// ---------------- scratch (device globals: allocation-free rule) ----------------
__device__ float g_P[(size_t)Nn * DD];
__device__ float g_Q[(size_t)Nn * DD];
__device__ float g_edge_m[(size_t)Ee * DD];
__device__ float g_edge_e[Ee];
__device__ float g_erow[Nn];
__device__ float g_denom[Nn];
__device__ float g_numrow[Nn];
__device__ float g_rank[Nn];
__device__ float g_soft[Nn];
__device__ float g_Z;
__device__ int   g_maxbits;

__device__ __forceinline__ float lrelu(float x) { return x > 0.f ? x : LRA * x; }
__device__ __forceinline__ float fixz(float x) { return x == 0.f ? 1e-12f : x; }

// ---------------- K0: zero accumulators ----------------
__global__ void k_zero(float* __restrict__ out) {
    int idx = blockIdx.x * 256 + threadIdx.x;
    if (idx < Nn * DD) out[idx] = 0.f;
    if (idx < Nn) { g_erow[idx] = 0.f; g_denom[idx] = 0.f; g_numrow[idx] = 0.f; }
    if (idx == 0) { g_Z = 0.f; g_maxbits = 0; }
}

// ================= GEMM tiles: 128 rows x 64 cols, 256 threads, 4x8 microtile =================
// tx = tid & 7 (8 col-groups of 8), ty = tid >> 3 (32 row-groups of 4).

// ---------------- K1: node GEMM: C[n][j] = sum_k X[n][k]*a[j][KOFF+k] ----------------
template <int KOFF, int WHICH>   // WHICH: 0 -> g_P, 1 -> g_Q
__global__ __launch_bounds__(256, 4) void k_node_gemm(const float* __restrict__ X,
                                                      const float* __restrict__ a) {
    __shared__ float sx[128 * 64];   // 32 KB
    __shared__ float sw[64 * 64];    // 16 KB
    float* __restrict__ C = WHICH == 0 ? g_P : g_Q;
    int tid = threadIdx.x;
    int tx = tid & 7, ty = tid >> 3;
    int n0 = blockIdx.x * 128;

    const float4* Xv = (const float4*)X;
    float4* sxv = (float4*)sx;
    for (int i = tid; i < 128 * 16; i += 256) {
        int r = i >> 4, kq = i & 15;
        int n = n0 + r; if (n >= Nn) n = Nn - 1;
        sxv[i] = Xv[(size_t)n * 16 + kq];
    }
    for (int i = tid; i < 64 * 16; i += 256) {
        int j = i & 63, k4 = i >> 6;
        float4 v = *(const float4*)(a + j * 192 + KOFF + k4 * 4);
        sw[(k4 * 4 + 0) * 64 + j] = v.x;
        sw[(k4 * 4 + 1) * 64 + j] = v.y;
        sw[(k4 * 4 + 2) * 64 + j] = v.z;
        sw[(k4 * 4 + 3) * 64 + j] = v.w;
    }
    __syncthreads();

    int r0 = ty * 4, c0 = tx * 8;
    float acc[4][8] = {};
#pragma unroll 2
    for (int k4 = 0; k4 < 16; k4++) {
        float4 xv[4];
#pragma unroll
        for (int i = 0; i < 4; i++)
            xv[i] = *(const float4*)&sx[(r0 + i) * 64 + k4 * 4];
#pragma unroll
        for (int k = 0; k < 4; k++) {
            float4 wa = *(const float4*)&sw[(k4 * 4 + k) * 64 + c0];
            float4 wb = *(const float4*)&sw[(k4 * 4 + k) * 64 + c0 + 4];
#pragma unroll
            for (int i = 0; i < 4; i++) {
                float xk = k == 0 ? xv[i].x : k == 1 ? xv[i].y : k == 2 ? xv[i].z : xv[i].w;
                acc[i][0] += xk * wa.x; acc[i][1] += xk * wa.y;
                acc[i][2] += xk * wa.z; acc[i][3] += xk * wa.w;
                acc[i][4] += xk * wb.x; acc[i][5] += xk * wb.y;
                acc[i][6] += xk * wb.z; acc[i][7] += xk * wb.w;
            }
        }
    }
#pragma unroll
    for (int i = 0; i < 4; i++) {
        int n = n0 + r0 + i;
        if (n < Nn) {
            *(float4*)&C[(size_t)n * DD + c0] =
                make_float4(acc[i][0], acc[i][1], acc[i][2], acc[i][3]);
            *(float4*)&C[(size_t)n * DD + c0 + 4] =
                make_float4(acc[i][4], acc[i][5], acc[i][6], acc[i][7]);
        }
    }
}

// ---------------- K2: edge GEMM + attention epilogue ----------------
// E = 6250*128 exactly (no tail).
__global__ __launch_bounds__(256, 4) void k_edge_gemm(const float* __restrict__ emb,
                                                      const float* __restrict__ a,
                                                      const float* __restrict__ a2,
                                                      const int* __restrict__ src,
                                                      const int* __restrict__ dst) {
    __shared__ float sx[128 * 64];   // 32 KB
    __shared__ float sw[64 * 64];    // 16 KB
    int tid = threadIdx.x;
    int tx = tid & 7, ty = tid >> 3;
    size_t e0 = (size_t)blockIdx.x * 128;

    const float4* embv = (const float4*)emb + e0 * 16;
    float4* sxv = (float4*)sx;
    for (int i = tid; i < 128 * 16; i += 256) sxv[i] = embv[i];
    for (int i = tid; i < 64 * 16; i += 256) {
        int j = i & 63, k4 = i >> 6;
        float4 v = *(const float4*)(a + j * 192 + 128 + k4 * 4);
        sw[(k4 * 4 + 0) * 64 + j] = v.x;
        sw[(k4 * 4 + 1) * 64 + j] = v.y;
        sw[(k4 * 4 + 2) * 64 + j] = v.z;
        sw[(k4 * 4 + 3) * 64 + j] = v.w;
    }
    __syncthreads();

    int r0 = ty * 4, c0 = tx * 8;
    float acc[4][8] = {};
#pragma unroll 2
    for (int k4 = 0; k4 < 16; k4++) {
        float4 xv[4];
#pragma unroll
        for (int i = 0; i < 4; i++)
            xv[i] = *(const float4*)&sx[(r0 + i) * 64 + k4 * 4];
#pragma unroll
        for (int k = 0; k < 4; k++) {
            float4 wa = *(const float4*)&sw[(k4 * 4 + k) * 64 + c0];
            float4 wb = *(const float4*)&sw[(k4 * 4 + k) * 64 + c0 + 4];
#pragma unroll
            for (int i = 0; i < 4; i++) {
                float xk = k == 0 ? xv[i].x : k == 1 ? xv[i].y : k == 2 ? xv[i].z : xv[i].w;
                acc[i][0] += xk * wa.x; acc[i][1] += xk * wa.y;
                acc[i][2] += xk * wa.z; acc[i][3] += xk * wa.w;
                acc[i][4] += xk * wb.x; acc[i][5] += xk * wb.y;
                acc[i][6] += xk * wb.z; acc[i][7] += xk * wb.w;
            }
        }
    }

    // epilogue: add P[src]+Q[dst], leakyrelu, store edge_m, reduce powers over tx (8 lanes)
    float4 a2a = *(const float4*)(a2 + c0);
    float4 a2b = *(const float4*)(a2 + c0 + 4);
    float pw[4];
#pragma unroll
    for (int i = 0; i < 4; i++) {
        int rl = r0 + i;
        size_t e = e0 + rl;
        int s = src[e], d = dst[e];   // uniform across tx group -> broadcast
        float4 pa = *(const float4*)&g_P[(size_t)s * DD + c0];
        float4 pb = *(const float4*)&g_P[(size_t)s * DD + c0 + 4];
        float4 qa = *(const float4*)&g_Q[(size_t)d * DD + c0];
        float4 qb = *(const float4*)&g_Q[(size_t)d * DD + c0 + 4];
        float v0 = lrelu(acc[i][0] + pa.x + qa.x);
        float v1 = lrelu(acc[i][1] + pa.y + qa.y);
        float v2 = lrelu(acc[i][2] + pa.z + qa.z);
        float v3 = lrelu(acc[i][3] + pa.w + qa.w);
        float v4 = lrelu(acc[i][4] + pb.x + qb.x);
        float v5 = lrelu(acc[i][5] + pb.y + qb.y);
        float v6 = lrelu(acc[i][6] + pb.z + qb.z);
        float v7 = lrelu(acc[i][7] + pb.w + qb.w);
        *(float4*)&g_edge_m[e * DD + c0]     = make_float4(v0, v1, v2, v3);
        *(float4*)&g_edge_m[e * DD + c0 + 4] = make_float4(v4, v5, v6, v7);
        pw[i] = v0 * a2a.x + v1 * a2a.y + v2 * a2a.z + v3 * a2a.w
              + v4 * a2b.x + v5 * a2b.y + v6 * a2b.z + v7 * a2b.w;
    }
#pragma unroll
    for (int m = 4; m >= 1; m >>= 1)
#pragma unroll
        for (int i = 0; i < 4; i++)
            pw[i] += __shfl_xor_sync(0xffffffffu, pw[i], m);   // reduce over 8-lane tx group
    if (tx == 0) {
#pragma unroll
        for (int i = 0; i < 4; i++) {
            size_t e = e0 + r0 + i;
            float p = -lrelu(pw[i]);
            float ee = expf(p);
            g_edge_e[e] = ee;
            atomicAdd(&g_erow[dst[e]], ee);
        }
    }
}

// ---------------- K3: denom accumulation ----------------
__global__ void k_rel(const int* __restrict__ src) {
    int e = blockIdx.x * 256 + threadIdx.x;
    if (e >= Ee) return;
    int s = src[e];
    atomicAdd(&g_denom[s], g_edge_e[e] / fixz(g_erow[s]));
}

// ---------------- K4: num + num_rowsum (rel recomputed) ----------------
__global__ void k_num(const int* __restrict__ src, const int* __restrict__ dst,
                      const float* __restrict__ rank_in) {
    int e = blockIdx.x * 256 + threadIdx.x;
    if (e >= Ee) return;
    int s = src[e];
    float rel = g_edge_e[e] / fixz(g_erow[s]);
    float num = rel * rank_in[s] / fixz(g_denom[s]);
    atomicAdd(&g_numrow[dst[e]], num);
}

// ---------------- K5a: rank_new + global max ----------------
__global__ void k_rank_max() {
    __shared__ float sm[8];
    int idx = blockIdx.x * 256 + threadIdx.x;
    float r = -1e30f;
    if (idx < Nn) {
        r = 0.15f + 0.85f * g_numrow[idx];
        g_rank[idx] = r;
    }
    float v = r;
#pragma unroll
    for (int m = 16; m >= 1; m >>= 1) v = fmaxf(v, __shfl_xor_sync(0xffffffffu, v, m));
    if ((threadIdx.x & 31) == 0) sm[threadIdx.x >> 5] = v;
    __syncthreads();
    if (threadIdx.x < 8) {
        v = sm[threadIdx.x];
#pragma unroll
        for (int m = 4; m >= 1; m >>= 1) v = fmaxf(v, __shfl_xor_sync(0xffu, v, m));
        if (threadIdx.x == 0) atomicMax(&g_maxbits, __float_as_int(v)); // values > 0
    }
}

// ---------------- K5b: exp + global sum (g_soft stays unnormalized) ----------------
__global__ void k_softmax_sum() {
    __shared__ float sm[8];
    int idx = blockIdx.x * 256 + threadIdx.x;
    float mx = __int_as_float(g_maxbits);
    float t = 0.f;
    if (idx < Nn) {
        t = expf(g_rank[idx] - mx);
        g_soft[idx] = t;
    }
    float v = t;
#pragma unroll
    for (int m = 16; m >= 1; m >>= 1) v += __shfl_xor_sync(0xffffffffu, v, m);
    if ((threadIdx.x & 31) == 0) sm[threadIdx.x >> 5] = v;
    __syncthreads();
    if (threadIdx.x < 8) {
        v = sm[threadIdx.x];
#pragma unroll
        for (int m = 4; m >= 1; m >>= 1) v += __shfl_xor_sync(0xffu, v, m);
        if (threadIdx.x == 0) atomicAdd(&g_Z, v);
    }
}

// ---------------- K6: weighted feature scatter (red.v4, softmax scale fused) ----------------
__global__ void k_scatter(const int* __restrict__ src, const int* __restrict__ dst,
                          float* __restrict__ out) {
    int idx = blockIdx.x * 256 + threadIdx.x;   // E*16 = 12.8M
    int e = idx >> 4, g = idx & 15;
    float s = g_soft[src[e]] * g_edge_e[e] / g_Z;  // uniform across the 16-lane group
    float4 m = *(const float4*)&g_edge_m[((size_t)e << 6) + g * 4];
    float* p = &out[((size_t)dst[e] << 6) + g * 4];
    asm volatile("red.global.add.v4.f32 [%0], {%1,%2,%3,%4};"
                 :: "l"(p), "f"(s * m.x), "f"(s * m.y), "f"(s * m.z), "f"(s * m.w)
                 : "memory");
}

// ---------------- K7: finalize ----------------
__global__ void k_finalize(float* __restrict__ out) {
    int idx = blockIdx.x * 256 + threadIdx.x;
    if (idx < Nn * DD) {
        int n = idx >> 6;
        float h = out[idx] / fixz(g_erow[n]);
        out[idx] = h > 0.f ? h : expm1f(h);
    }
    if (idx < Nn) out[(size_t)Nn * DD + idx] = g_rank[idx];
}

// ---------------- launcher ----------------
extern "C" void kernel_launch(void* const* d_in, const int* in_sizes, int n_in,
                              void* d_out, int out_size) {
    const float* input   = (const float*)d_in[0];
    const int*   edge    = (const int*)d_in[1];
    const float* emb     = (const float*)d_in[2];
    const float* rank_in = (const float*)d_in[3];
    const float* a       = (const float*)d_in[4];
    const float* a2      = (const float*)d_in[5];
    const int* src = edge;
    const int* dst = edge + Ee;
    float* out = (float*)d_out;

    int nodeBlk = (Nn + 127) / 128;        // 391
    int edgeBlk = Ee / 128;                // 6250
    int eThrBlk = (Ee + 255) / 256;        // 3125
    int nThrBlk = (Nn + 255) / 256;        // 196
    int zBlk    = (Nn * DD + 255) / 256;   // 12500
    int scatBlk = (Ee * 16) / 256;         // 50000

    k_zero<<<zBlk, 256>>>(out);
    k_node_gemm<0, 0><<<nodeBlk, 256>>>(input, a);
    k_node_gemm<64, 1><<<nodeBlk, 256>>>(input, a);
    k_edge_gemm<<<edgeBlk, 256>>>(emb, a, a2, src, dst);
    k_rel<<<eThrBlk, 256>>>(src);
    k_num<<<eThrBlk, 256>>>(src, dst, rank_in);
    k_rank_max<<<nThrBlk, 256>>>();
    k_softmax_sum<<<nThrBlk, 256>>>();
    k_scatter<<<scatBlk, 256>>>(src, dst, out);
    k_finalize<<<zBlk, 256>>>(out);
}